// round 4
// baseline (speedup 1.0000x reference)
#include <cuda_runtime.h>
#include <cstdint>

#define NNODES 8192
#define FEATD  1024
#define HDIM   512
#define GDIM   (5*HDIM)
#define NCTA   128
#define WPC    4                 // warps per CTA; 1 warp = 1 hidden unit
#define NTHR   (WPC*32)
#define SENT   0xFFC0DEADu      // NaN-payload sentinel (legit h is never NaN)

// Scratch (static __device__ arrays: allocation-free per harness rules)
__device__ float g_xgb[(size_t)NNODES * GDIM];   // Wx·x + bx + bh   [N,5H]
__device__ float g_pxb[(size_t)NNODES * HDIM];   // Wpx·x + bpx      [N,H]
__device__ float g_C[(size_t)NNODES * HDIM];     // cell states      [N,H]

__device__ __forceinline__ float sigm(float x) {
    return 1.0f / (1.0f + __expf(-x));
}
__device__ __forceinline__ float tanhfast(float x) {
    // tanh(x) = 1 - 2/(e^{2x}+1); saturates cleanly (no NaN/Inf in result)
    return 1.0f - 2.0f / (__expf(2.0f * x) + 1.0f);
}

__device__ __forceinline__ float4 ld_volatile_f4(const float* p) {
    float4 v;
    asm volatile("ld.volatile.global.v4.f32 {%0,%1,%2,%3}, [%4];"
                 : "=f"(v.x), "=f"(v.y), "=f"(v.z), "=f"(v.w) : "l"(p) : "memory");
    return v;
}

// ---------------------------------------------------------------------------
// Poison d_out with the sentinel each launch (makes polling replay-safe).
// ---------------------------------------------------------------------------
__global__ void poison_kernel(float4* __restrict__ out) {
    int i = blockIdx.x * blockDim.x + threadIdx.x;   // 1,048,576 float4s
    float f = __uint_as_float(SENT);
    out[i] = make_float4(f, f, f, f);
}

// ---------------------------------------------------------------------------
// Batched precompute GEMM:  C[M,N] = A[M,K] * B[N,K]^T + b1[N] (+ b2[N])
// 128x128x8 SMEM-tiled fp32, 256 threads, 8x8 per-thread tile.
// ---------------------------------------------------------------------------
__global__ __launch_bounds__(256) void sgemm_bt_bias(
    const float* __restrict__ A, const float* __restrict__ B,
    const float* __restrict__ b1, const float* __restrict__ b2,
    float* __restrict__ C, int M, int N, int K)
{
    const int BM = 128, BN = 128;
    __shared__ float As[8][BM + 4];
    __shared__ float Bs[8][BN + 4];

    const int tid = threadIdx.x;
    const int bxi = blockIdx.x, byi = blockIdx.y;
    const int loadRow = tid >> 1;
    const int loadCol = (tid & 1) << 2;

    const float* Ab = A + (size_t)byi * BM * K;
    const float* Bb = B + (size_t)bxi * BN * K;

    const int ty = tid >> 4;
    const int tx = tid & 15;

    float acc[8][8];
#pragma unroll
    for (int i = 0; i < 8; i++)
#pragma unroll
        for (int j = 0; j < 8; j++) acc[i][j] = 0.0f;

    for (int k0 = 0; k0 < K; k0 += 8) {
        float4 av = *(const float4*)(Ab + (size_t)loadRow * K + k0 + loadCol);
        float4 bv = *(const float4*)(Bb + (size_t)loadRow * K + k0 + loadCol);
        As[loadCol + 0][loadRow] = av.x;
        As[loadCol + 1][loadRow] = av.y;
        As[loadCol + 2][loadRow] = av.z;
        As[loadCol + 3][loadRow] = av.w;
        Bs[loadCol + 0][loadRow] = bv.x;
        Bs[loadCol + 1][loadRow] = bv.y;
        Bs[loadCol + 2][loadRow] = bv.z;
        Bs[loadCol + 3][loadRow] = bv.w;
        __syncthreads();

#pragma unroll
        for (int k = 0; k < 8; k++) {
            float ar[8], br[8];
#pragma unroll
            for (int i = 0; i < 8; i++) ar[i] = As[k][ty * 8 + i];
#pragma unroll
            for (int j = 0; j < 8; j++) br[j] = Bs[k][tx * 8 + j];
#pragma unroll
            for (int i = 0; i < 8; i++)
#pragma unroll
                for (int j = 0; j < 8; j++)
                    acc[i][j] = fmaf(ar[i], br[j], acc[i][j]);
        }
        __syncthreads();
    }

#pragma unroll
    for (int i = 0; i < 8; i++) {
        int m = byi * BM + ty * 8 + i;
        int nbase = bxi * BN + tx * 8;
        float v[8];
#pragma unroll
        for (int j = 0; j < 8; j++) {
            v[j] = acc[i][j] + b1[nbase + j];
            if (b2) v[j] += b2[nbase + j];
        }
        float4* out = (float4*)(C + (size_t)m * N + nbase);
        out[0] = make_float4(v[0], v[1], v[2], v[3]);
        out[1] = make_float4(v[4], v[5], v[6], v[7]);
    }
}

// ---------------------------------------------------------------------------
// Persistent serial recurrence. 128 CTAs x 128 threads; warp = 1 hidden unit.
// Warp keeps all 5 Wh rows of its unit in 80 registers. No barriers, no
// atomics: readiness of h[parent] is detected by polling the data itself
// against the sentinel (poison_kernel pre-fills d_out each launch).
// ---------------------------------------------------------------------------
__global__ __launch_bounds__(NTHR, 1) void treelstm_seq_kernel(
    const float* __restrict__ Wh, const int* __restrict__ parents,
    float* __restrict__ Hout)
{
    const int cta  = blockIdx.x;
    const int w    = threadIdx.x >> 5;
    const int lane = threadIdx.x & 31;
    const int unit = cta * WPC + w;

    // Pin this unit's 5 Wh rows in registers: lane covers k = 4*lane + 128*c.
    float4 wv[5][4];
#pragma unroll
    for (int g = 0; g < 5; g++) {
        const float* wrow = Wh + (size_t)(g * HDIM + unit) * HDIM + 4 * lane;
#pragma unroll
        for (int c = 0; c < 4; c++)
            wv[g][c] = *(const float4*)(wrow + 128 * c);
    }

    // Prefetch node-0 static terms (lane 0 only uses them)
    float xg[5], px = 0.0f;
#pragma unroll
    for (int g = 0; g < 5; g++) xg[g] = 0.0f;
    if (lane == 0) {
#pragma unroll
        for (int g = 0; g < 5; g++) xg[g] = g_xgb[(size_t)(g * HDIM + unit)];
        px = g_pxb[unit];
    }

    float c_last = 0.0f;

    for (int t = 0; t < NNODES; t++) {
        const int p = parents[t];

        // --- acquire h[parent]: poll the data itself (fused detect+load) ---
        float4 h0, h1, h2, h3;
        if (p >= 0) {
            const float* rowp = Hout + (size_t)p * HDIM + 4 * lane;
            for (;;) {
                h0 = ld_volatile_f4(rowp + 0);
                h1 = ld_volatile_f4(rowp + 128);
                h2 = ld_volatile_f4(rowp + 256);
                h3 = ld_volatile_f4(rowp + 384);
                bool ok =
                    (__float_as_uint(h0.x) != SENT) & (__float_as_uint(h0.y) != SENT) &
                    (__float_as_uint(h0.z) != SENT) & (__float_as_uint(h0.w) != SENT) &
                    (__float_as_uint(h1.x) != SENT) & (__float_as_uint(h1.y) != SENT) &
                    (__float_as_uint(h1.z) != SENT) & (__float_as_uint(h1.w) != SENT) &
                    (__float_as_uint(h2.x) != SENT) & (__float_as_uint(h2.y) != SENT) &
                    (__float_as_uint(h2.z) != SENT) & (__float_as_uint(h2.w) != SENT) &
                    (__float_as_uint(h3.x) != SENT) & (__float_as_uint(h3.y) != SENT) &
                    (__float_as_uint(h3.z) != SENT) & (__float_as_uint(h3.w) != SENT);
                if (__all_sync(0xffffffffu, ok)) break;
            }
        } else {
            h0 = h1 = h2 = h3 = make_float4(0.f, 0.f, 0.f, 0.f);
        }

        // --- 5 dot products (this unit's i,o,f,u,r rows) ---
        float acc[5];
#pragma unroll
        for (int g = 0; g < 5; g++) {
            float a0 = fmaf(wv[g][0].x, h0.x, fmaf(wv[g][0].y, h0.y,
                       fmaf(wv[g][0].z, h0.z, wv[g][0].w * h0.w)));
            float a1 = fmaf(wv[g][1].x, h1.x, fmaf(wv[g][1].y, h1.y,
                       fmaf(wv[g][1].z, h1.z, wv[g][1].w * h1.w)));
            float a2 = fmaf(wv[g][2].x, h2.x, fmaf(wv[g][2].y, h2.y,
                       fmaf(wv[g][2].z, h2.z, wv[g][2].w * h2.w)));
            float a3 = fmaf(wv[g][3].x, h3.x, fmaf(wv[g][3].y, h3.y,
                       fmaf(wv[g][3].z, h3.z, wv[g][3].w * h3.w)));
            acc[g] = (a0 + a1) + (a2 + a3);
        }

        // --- fused 5-way butterfly reduce (5 independent chains pipeline) ---
#pragma unroll
        for (int off = 16; off; off >>= 1) {
#pragma unroll
            for (int g = 0; g < 5; g++)
                acc[g] += __shfl_xor_sync(0xffffffffu, acc[g], off);
        }

        // --- gate math + state update + publish (lane 0) ---
        if (lane == 0) {
            float cpar = 0.0f;
            if (p >= 0)
                cpar = (p == t - 1) ? c_last : g_C[(size_t)p * HDIM + unit];
            float iv = sigm(acc[0] + xg[0]);
            float ov = sigm(acc[1] + xg[1]);
            float fv = sigm(acc[2] + xg[2]);
            float uv = tanhfast(acc[3] + xg[3]);
            float rv = sigm(acc[4] + xg[4]);
            float c  = fmaf(fv, cpar, iv * uv);
            float hh = ov * tanhfast(c);
            float hf = rv * hh + (1.0f - rv) * px;
            if (__float_as_uint(hf) == SENT)          // impossible unless NaN
                hf = __uint_as_float(SENT ^ 1u);
            c_last = c;
            g_C[(size_t)t * HDIM + unit]  = c;
            Hout[(size_t)t * HDIM + unit] = hf;        // publish (write-through to L2)
        }

        // --- prefetch next node's static terms (hides under next poll) ---
        if (lane == 0 && t + 1 < NNODES) {
#pragma unroll
            for (int g = 0; g < 5; g++)
                xg[g] = g_xgb[(size_t)(t + 1) * GDIM + g * HDIM + unit];
            px = g_pxb[(size_t)(t + 1) * HDIM + unit];
        }
    }
}

extern "C" void kernel_launch(void* const* d_in, const int* in_sizes, int n_in,
                              void* d_out, int out_size) {
    const float* features = (const float*)d_in[0];
    const int*   parents  = (const int*)d_in[1];
    const float* Wpx      = (const float*)d_in[2];
    const float* bpx      = (const float*)d_in[3];
    const float* Wx       = (const float*)d_in[4];
    const float* bx       = (const float*)d_in[5];
    const float* Wh       = (const float*)d_in[6];
    const float* bh       = (const float*)d_in[7];
    float* Hout = (float*)d_out;

    float* d_pxb = nullptr;
    float* d_xgb = nullptr;
    cudaGetSymbolAddress((void**)&d_pxb, g_pxb);
    cudaGetSymbolAddress((void**)&d_xgb, g_xgb);

    // 1) sentinel-poison the output buffer (replay-safe readiness protocol)
    poison_kernel<<<(NNODES * HDIM / 4) / 256, 256>>>((float4*)Hout);

    // 2) batched x-side projections
    dim3 gpx(HDIM / 128, NNODES / 128);
    sgemm_bt_bias<<<gpx, 256>>>(features, Wpx, bpx, nullptr, d_pxb,
                                NNODES, HDIM, FEATD);
    dim3 gxg(GDIM / 128, NNODES / 128);
    sgemm_bt_bias<<<gxg, 256>>>(features, Wx, bx, bh, d_xgb,
                                NNODES, GDIM, FEATD);

    // 3) serial recurrence (barrier-free dataflow, 128 co-resident CTAs)
    treelstm_seq_kernel<<<NCTA, NTHR>>>(Wh, parents, Hout);
}

// round 5
// speedup vs baseline: 3.6441x; 3.6441x over previous
#include <cuda_runtime.h>
#include <cstdint>

#define NNODES 8192
#define FEATD  1024
#define HDIM   512
#define GDIM   (5*HDIM)
#define NCTA   128
#define WPC    4                 // warps per CTA; warp w owns unit cta*4+w
#define NTHR   (WPC*32)
#define SENT   0xFFC0DEADu      // NaN-payload sentinel (legit values never NaN)

// Scratch (static __device__ arrays: allocation-free per harness rules)
__device__ float g_xgb[(size_t)NNODES * GDIM];   // Wx·x + bx + bh   [N,5H]
__device__ float g_pxb[(size_t)NNODES * HDIM];   // Wpx·x + bpx      [N,H]
__device__ float g_C[(size_t)NNODES * HDIM];     // cell states      [N,H]

__device__ __forceinline__ float sigm(float x) {
    return 1.0f / (1.0f + __expf(-x));
}
__device__ __forceinline__ float tanhfast(float x) {
    // tanh(x) = 1 - 2/(e^{2x}+1); saturates cleanly (no NaN/Inf in result)
    return 1.0f - 2.0f / (__expf(2.0f * x) + 1.0f);
}

__device__ __forceinline__ float4 ld_volatile_f4(const float* p) {
    float4 v;
    asm volatile("ld.volatile.global.v4.f32 {%0,%1,%2,%3}, [%4];"
                 : "=f"(v.x), "=f"(v.y), "=f"(v.z), "=f"(v.w) : "l"(p) : "memory");
    return v;
}
__device__ __forceinline__ float ld_volatile_f(const float* p) {
    float v;
    asm volatile("ld.volatile.global.f32 %0, [%1];" : "=f"(v) : "l"(p) : "memory");
    return v;
}
// value sanitizer: result may never bit-equal the sentinel (it's a NaN payload;
// results are never NaN, but guard the measure-zero case anyway)
__device__ __forceinline__ float desent(float v) {
    return (__float_as_uint(v) == SENT) ? __uint_as_float(SENT ^ 1u) : v;
}

// ---------------------------------------------------------------------------
// Poison Hout and g_C with the sentinel each launch (replay-safe protocol).
// ---------------------------------------------------------------------------
__global__ void poison_kernel(float4* __restrict__ a, float4* __restrict__ b) {
    int i = blockIdx.x * blockDim.x + threadIdx.x;   // 2 * 1,048,576 float4s
    float f = __uint_as_float(SENT);
    float4 v = make_float4(f, f, f, f);
    const int HALF = NNODES * HDIM / 4;
    if (i < HALF) a[i] = v;
    else          b[i - HALF] = v;
}

// ---------------------------------------------------------------------------
// Batched precompute GEMM:  C[M,N] = A[M,K] * B[N,K]^T + b1[N] (+ b2[N])
// 128x128x8 SMEM-tiled fp32, 256 threads, 8x8 per-thread tile.
// ---------------------------------------------------------------------------
__global__ __launch_bounds__(256) void sgemm_bt_bias(
    const float* __restrict__ A, const float* __restrict__ B,
    const float* __restrict__ b1, const float* __restrict__ b2,
    float* __restrict__ C, int M, int N, int K)
{
    const int BM = 128, BN = 128;
    __shared__ float As[8][BM + 4];
    __shared__ float Bs[8][BN + 4];

    const int tid = threadIdx.x;
    const int bxi = blockIdx.x, byi = blockIdx.y;
    const int loadRow = tid >> 1;
    const int loadCol = (tid & 1) << 2;

    const float* Ab = A + (size_t)byi * BM * K;
    const float* Bb = B + (size_t)bxi * BN * K;

    const int ty = tid >> 4;
    const int tx = tid & 15;

    float acc[8][8];
#pragma unroll
    for (int i = 0; i < 8; i++)
#pragma unroll
        for (int j = 0; j < 8; j++) acc[i][j] = 0.0f;

    for (int k0 = 0; k0 < K; k0 += 8) {
        float4 av = *(const float4*)(Ab + (size_t)loadRow * K + k0 + loadCol);
        float4 bv = *(const float4*)(Bb + (size_t)loadRow * K + k0 + loadCol);
        As[loadCol + 0][loadRow] = av.x;
        As[loadCol + 1][loadRow] = av.y;
        As[loadCol + 2][loadRow] = av.z;
        As[loadCol + 3][loadRow] = av.w;
        Bs[loadCol + 0][loadRow] = bv.x;
        Bs[loadCol + 1][loadRow] = bv.y;
        Bs[loadCol + 2][loadRow] = bv.z;
        Bs[loadCol + 3][loadRow] = bv.w;
        __syncthreads();

#pragma unroll
        for (int k = 0; k < 8; k++) {
            float ar[8], br[8];
#pragma unroll
            for (int i = 0; i < 8; i++) ar[i] = As[k][ty * 8 + i];
#pragma unroll
            for (int j = 0; j < 8; j++) br[j] = Bs[k][tx * 8 + j];
#pragma unroll
            for (int i = 0; i < 8; i++)
#pragma unroll
                for (int j = 0; j < 8; j++)
                    acc[i][j] = fmaf(ar[i], br[j], acc[i][j]);
        }
        __syncthreads();
    }

#pragma unroll
    for (int i = 0; i < 8; i++) {
        int m = byi * BM + ty * 8 + i;
        int nbase = bxi * BN + tx * 8;
        float v[8];
#pragma unroll
        for (int j = 0; j < 8; j++) {
            v[j] = acc[i][j] + b1[nbase + j];
            if (b2) v[j] += b2[nbase + j];
        }
        float4* out = (float4*)(C + (size_t)m * N + nbase);
        out[0] = make_float4(v[0], v[1], v[2], v[3]);
        out[1] = make_float4(v[4], v[5], v[6], v[7]);
    }
}

// ---------------------------------------------------------------------------
// Persistent serial recurrence. 128 CTAs x 128 threads; warp w owns unit
// cta*4+w (all 5 gates, 80 weight registers). Readiness protocol: data-is-flag
// (sentinel), but ONLY warp0 polls globally (128 chip-wide pollers); the row
// is then shared intra-CTA through SMEM. The CTA publishes its 4 h values as
// a single 16B vector store (each 32b word is either sentinel or final, so
// no fences are needed anywhere).
// ---------------------------------------------------------------------------
__global__ __launch_bounds__(NTHR, 1) void treelstm_seq_kernel(
    const float* __restrict__ Wh, const int* __restrict__ parents,
    float* __restrict__ Hout)
{
    __shared__ float4 s_h[128];      // shared copy of h[parent] (2KB)
    __shared__ float4 s_hfv;         // 4 finished h values, staged for publish

    const int cta  = blockIdx.x;
    const int w    = threadIdx.x >> 5;
    const int lane = threadIdx.x & 31;
    const int unit = cta * WPC + w;

    // Pin this unit's 5 Wh rows in registers: lane covers k = 4*lane + 128*c.
    float4 wv[5][4];
#pragma unroll
    for (int g = 0; g < 5; g++) {
        const float* wrow = Wh + (size_t)(g * HDIM + unit) * HDIM + 4 * lane;
#pragma unroll
        for (int c = 0; c < 4; c++)
            wv[g][c] = *(const float4*)(wrow + 128 * c);
    }

    // Prefetch node-0 static terms (lane 0 only uses them)
    float xg[5], px = 0.0f;
#pragma unroll
    for (int g = 0; g < 5; g++) xg[g] = 0.0f;
    if (lane == 0) {
#pragma unroll
        for (int g = 0; g < 5; g++) xg[g] = g_xgb[(size_t)(g * HDIM + unit)];
        px = g_pxb[unit];
    }

    float c_last = 0.0f;

    for (int t = 0; t < NNODES; t++) {
        const int p = parents[t];

        float4 h0, h1, h2, h3;
        if (p >= 0 && w == 0) {
            // --- warp0: fused detect+load of h[parent] (global, volatile) ---
            const float* rowp = Hout + (size_t)p * HDIM + 4 * lane;
            for (;;) {
                h0 = ld_volatile_f4(rowp + 0);
                h1 = ld_volatile_f4(rowp + 128);
                h2 = ld_volatile_f4(rowp + 256);
                h3 = ld_volatile_f4(rowp + 384);
                bool ok =
                    (__float_as_uint(h0.x) != SENT) & (__float_as_uint(h0.y) != SENT) &
                    (__float_as_uint(h0.z) != SENT) & (__float_as_uint(h0.w) != SENT) &
                    (__float_as_uint(h1.x) != SENT) & (__float_as_uint(h1.y) != SENT) &
                    (__float_as_uint(h1.z) != SENT) & (__float_as_uint(h1.w) != SENT) &
                    (__float_as_uint(h2.x) != SENT) & (__float_as_uint(h2.y) != SENT) &
                    (__float_as_uint(h2.z) != SENT) & (__float_as_uint(h2.w) != SENT) &
                    (__float_as_uint(h3.x) != SENT) & (__float_as_uint(h3.y) != SENT) &
                    (__float_as_uint(h3.z) != SENT) & (__float_as_uint(h3.w) != SENT);
                if (__all_sync(0xffffffffu, ok)) break;
            }
            // share with warps 1..3
            s_h[lane +  0] = h0;
            s_h[lane + 32] = h1;
            s_h[lane + 64] = h2;
            s_h[lane + 96] = h3;
        }
        __syncthreads();                       // bar A: s_h ready
        if (p >= 0) {
            if (w != 0) {
                h0 = s_h[lane +  0];
                h1 = s_h[lane + 32];
                h2 = s_h[lane + 64];
                h3 = s_h[lane + 96];
            }
        } else {
            h0 = h1 = h2 = h3 = make_float4(0.f, 0.f, 0.f, 0.f);
        }

        // --- 5 dot products (this unit's i,o,f,u,r rows) ---
        float acc[5];
#pragma unroll
        for (int g = 0; g < 5; g++) {
            float a0 = fmaf(wv[g][0].x, h0.x, fmaf(wv[g][0].y, h0.y,
                       fmaf(wv[g][0].z, h0.z, wv[g][0].w * h0.w)));
            float a1 = fmaf(wv[g][1].x, h1.x, fmaf(wv[g][1].y, h1.y,
                       fmaf(wv[g][1].z, h1.z, wv[g][1].w * h1.w)));
            float a2 = fmaf(wv[g][2].x, h2.x, fmaf(wv[g][2].y, h2.y,
                       fmaf(wv[g][2].z, h2.z, wv[g][2].w * h2.w)));
            float a3 = fmaf(wv[g][3].x, h3.x, fmaf(wv[g][3].y, h3.y,
                       fmaf(wv[g][3].z, h3.z, wv[g][3].w * h3.w)));
            acc[g] = (a0 + a1) + (a2 + a3);
        }

        // --- fused 5-way butterfly reduce ---
#pragma unroll
        for (int off = 16; off; off >>= 1) {
#pragma unroll
            for (int g = 0; g < 5; g++)
                acc[g] += __shfl_xor_sync(0xffffffffu, acc[g], off);
        }

        // --- gate math + state update (lane 0 of each warp) ---
        if (lane == 0) {
            float cpar = 0.0f;
            if (p >= 0) {
                if (p == t - 1) {
                    cpar = c_last;                       // chain fast path
                } else {
                    const float* cp = &g_C[(size_t)p * HDIM + unit];
                    do { cpar = ld_volatile_f(cp); }     // general tree: sentinel poll
                    while (__float_as_uint(cpar) == SENT);
                }
            }
            float iv = sigm(acc[0] + xg[0]);
            float ov = sigm(acc[1] + xg[1]);
            float fv = sigm(acc[2] + xg[2]);
            float uv = tanhfast(acc[3] + xg[3]);
            float rv = sigm(acc[4] + xg[4]);
            float c  = desent(fmaf(fv, cpar, iv * uv));
            float hh = ov * tanhfast(c);
            float hf = desent(rv * hh + (1.0f - rv) * px);
            c_last = c;
            g_C[(size_t)t * HDIM + unit] = c;            // off critical path
            ((float*)&s_hfv)[w] = hf;                    // stage for publish
        }
        __syncthreads();                       // bar B: s_hfv complete

        // --- publish this CTA's 4 units as ONE 16B store ---
        if (w == 0 && lane == 0) {
            *(float4*)(Hout + (size_t)t * HDIM + cta * WPC) = s_hfv;
        }

        // --- prefetch next node's static terms (hidden under next poll) ---
        if (lane == 0 && t + 1 < NNODES) {
#pragma unroll
            for (int g = 0; g < 5; g++)
                xg[g] = g_xgb[(size_t)(t + 1) * GDIM + g * HDIM + unit];
            px = g_pxb[(size_t)(t + 1) * HDIM + unit];
        }
    }
}

extern "C" void kernel_launch(void* const* d_in, const int* in_sizes, int n_in,
                              void* d_out, int out_size) {
    const float* features = (const float*)d_in[0];
    const int*   parents  = (const int*)d_in[1];
    const float* Wpx      = (const float*)d_in[2];
    const float* bpx      = (const float*)d_in[3];
    const float* Wx       = (const float*)d_in[4];
    const float* bx       = (const float*)d_in[5];
    const float* Wh       = (const float*)d_in[6];
    const float* bh       = (const float*)d_in[7];
    float* Hout = (float*)d_out;

    float* d_pxb = nullptr;
    float* d_xgb = nullptr;
    float* d_C   = nullptr;
    cudaGetSymbolAddress((void**)&d_pxb, g_pxb);
    cudaGetSymbolAddress((void**)&d_xgb, g_xgb);
    cudaGetSymbolAddress((void**)&d_C,   g_C);

    // 1) sentinel-poison Hout and g_C (replay-safe readiness protocol)
    poison_kernel<<<(2 * NNODES * HDIM / 4) / 256, 256>>>((float4*)Hout,
                                                          (float4*)d_C);

    // 2) batched x-side projections
    dim3 gpx(HDIM / 128, NNODES / 128);
    sgemm_bt_bias<<<gpx, 256>>>(features, Wpx, bpx, nullptr, d_pxb,
                                NNODES, HDIM, FEATD);
    dim3 gxg(GDIM / 128, NNODES / 128);
    sgemm_bt_bias<<<gxg, 256>>>(features, Wx, bx, bh, d_xgb,
                                NNODES, GDIM, FEATD);

    // 3) serial recurrence (barrier-free dataflow, 128 co-resident CTAs)
    treelstm_seq_kernel<<<NCTA, NTHR>>>(Wh, parents, Hout);
}

// round 6
// speedup vs baseline: 5.1832x; 1.4224x over previous
#include <cuda_runtime.h>
#include <cstdint>

#define NNODES 8192
#define FEATD  1024
#define HDIM   512
#define GDIM   (5*HDIM)
#define NCTA   64
#define WPC    8                 // warps per CTA; warp w owns unit cta*8+w
#define NTHR   (WPC*32)
#define SENT   0xFFC0DEADu      // NaN-payload sentinel (legit values never NaN)

// Scratch (static __device__ arrays: allocation-free per harness rules)
__device__ float g_xgb[(size_t)NNODES * GDIM];   // Wx·x + bx + bh   [N,5H]
__device__ float g_pxb[(size_t)NNODES * HDIM];   // Wpx·x + bpx      [N,H]
__device__ float g_C[(size_t)NNODES * HDIM];     // cell states      [N,H]

__device__ __forceinline__ float sigm(float x) {
    return 1.0f / (1.0f + __expf(-x));
}
__device__ __forceinline__ float tanhfast(float x) {
    // tanh(x) = 1 - 2/(e^{2x}+1); saturates cleanly (no NaN/Inf in result)
    return 1.0f - 2.0f / (__expf(2.0f * x) + 1.0f);
}

__device__ __forceinline__ float4 ld_volatile_f4(const float* p) {
    float4 v;
    asm volatile("ld.volatile.global.v4.f32 {%0,%1,%2,%3}, [%4];"
                 : "=f"(v.x), "=f"(v.y), "=f"(v.z), "=f"(v.w) : "l"(p) : "memory");
    return v;
}
__device__ __forceinline__ float ld_volatile_f(const float* p) {
    float v;
    asm volatile("ld.volatile.global.f32 %0, [%1];" : "=f"(v) : "l"(p) : "memory");
    return v;
}
// result may never bit-equal the sentinel (NaN payload; results are never NaN,
// but guard the measure-zero case anyway)
__device__ __forceinline__ float desent(float v) {
    return (__float_as_uint(v) == SENT) ? __uint_as_float(SENT ^ 1u) : v;
}

// ---------------------------------------------------------------------------
// Poison Hout and g_C with the sentinel each launch (replay-safe protocol).
// ---------------------------------------------------------------------------
__global__ void poison_kernel(float4* __restrict__ a, float4* __restrict__ b) {
    int i = blockIdx.x * blockDim.x + threadIdx.x;   // 2 * 1,048,576 float4s
    float f = __uint_as_float(SENT);
    float4 v = make_float4(f, f, f, f);
    const int HALF = NNODES * HDIM / 4;
    if (i < HALF) a[i] = v;
    else          b[i - HALF] = v;
}

// ---------------------------------------------------------------------------
// Batched precompute GEMM:  C[M,N] = A[M,K] * B[N,K]^T + b1[N] (+ b2[N])
// 128x128x8 SMEM-tiled fp32, 256 threads, 8x8 per-thread tile.
// ---------------------------------------------------------------------------
__global__ __launch_bounds__(256) void sgemm_bt_bias(
    const float* __restrict__ A, const float* __restrict__ B,
    const float* __restrict__ b1, const float* __restrict__ b2,
    float* __restrict__ C, int M, int N, int K)
{
    const int BM = 128, BN = 128;
    __shared__ float As[8][BM + 4];
    __shared__ float Bs[8][BN + 4];

    const int tid = threadIdx.x;
    const int bxi = blockIdx.x, byi = blockIdx.y;
    const int loadRow = tid >> 1;
    const int loadCol = (tid & 1) << 2;

    const float* Ab = A + (size_t)byi * BM * K;
    const float* Bb = B + (size_t)bxi * BN * K;

    const int ty = tid >> 4;
    const int tx = tid & 15;

    float acc[8][8];
#pragma unroll
    for (int i = 0; i < 8; i++)
#pragma unroll
        for (int j = 0; j < 8; j++) acc[i][j] = 0.0f;

    for (int k0 = 0; k0 < K; k0 += 8) {
        float4 av = *(const float4*)(Ab + (size_t)loadRow * K + k0 + loadCol);
        float4 bv = *(const float4*)(Bb + (size_t)loadRow * K + k0 + loadCol);
        As[loadCol + 0][loadRow] = av.x;
        As[loadCol + 1][loadRow] = av.y;
        As[loadCol + 2][loadRow] = av.z;
        As[loadCol + 3][loadRow] = av.w;
        Bs[loadCol + 0][loadRow] = bv.x;
        Bs[loadCol + 1][loadRow] = bv.y;
        Bs[loadCol + 2][loadRow] = bv.z;
        Bs[loadCol + 3][loadRow] = bv.w;
        __syncthreads();

#pragma unroll
        for (int k = 0; k < 8; k++) {
            float ar[8], br[8];
#pragma unroll
            for (int i = 0; i < 8; i++) ar[i] = As[k][ty * 8 + i];
#pragma unroll
            for (int j = 0; j < 8; j++) br[j] = Bs[k][tx * 8 + j];
#pragma unroll
            for (int i = 0; i < 8; i++)
#pragma unroll
                for (int j = 0; j < 8; j++)
                    acc[i][j] = fmaf(ar[i], br[j], acc[i][j]);
        }
        __syncthreads();
    }

#pragma unroll
    for (int i = 0; i < 8; i++) {
        int m = byi * BM + ty * 8 + i;
        int nbase = bxi * BN + tx * 8;
        float v[8];
#pragma unroll
        for (int j = 0; j < 8; j++) {
            v[j] = acc[i][j] + b1[nbase + j];
            if (b2) v[j] += b2[nbase + j];
        }
        float4* out = (float4*)(C + (size_t)m * N + nbase);
        out[0] = make_float4(v[0], v[1], v[2], v[3]);
        out[1] = make_float4(v[4], v[5], v[6], v[7]);
    }
}

// ---------------------------------------------------------------------------
// Persistent serial recurrence. 64 CTAs x 256 threads; warp w owns unit
// cta*8+w (all 5 gates pinned in 80 regs). Readiness: data-is-flag (sentinel).
// Warps 0..3 each poll a 512B quarter of h[parent] (64 chip-wide readers per
// L2 line -> below slice saturation), share via SMEM; every warp's lane0
// publishes its h value directly (value IS the flag; no ordering needed).
// ---------------------------------------------------------------------------
__global__ __launch_bounds__(NTHR, 1) void treelstm_seq_kernel(
    const float* __restrict__ Wh, const int* __restrict__ parents,
    float* __restrict__ Hout)
{
    __shared__ float4 s_h[128];      // shared copy of h[parent] (2KB)

    const int cta  = blockIdx.x;
    const int w    = threadIdx.x >> 5;
    const int lane = threadIdx.x & 31;
    const int unit = cta * WPC + w;

    // Pin this unit's 5 Wh rows in registers: lane covers k = 4*lane + 128*c.
    float4 wv[5][4];
#pragma unroll
    for (int g = 0; g < 5; g++) {
        const float* wrow = Wh + (size_t)(g * HDIM + unit) * HDIM + 4 * lane;
#pragma unroll
        for (int c = 0; c < 4; c++)
            wv[g][c] = *(const float4*)(wrow + 128 * c);
    }

    // Prefetch node-0 static terms (lane 0 only uses them)
    float xg[5], px = 0.0f;
#pragma unroll
    for (int g = 0; g < 5; g++) xg[g] = 0.0f;
    if (lane == 0) {
#pragma unroll
        for (int g = 0; g < 5; g++) xg[g] = g_xgb[(size_t)(g * HDIM + unit)];
        px = g_pxb[unit];
    }

    float c_last = 0.0f;
    int p = parents[0];

    for (int t = 0; t < NNODES; t++) {
        const int p_next = (t + 1 < NNODES) ? parents[t + 1] : 0;

        float4 h0, h1, h2, h3;
        if (p >= 0) {
            // --- warps 0..3: fused detect+load, 512B quarter each ---
            if (w < 4) {
                const float* qp = Hout + (size_t)p * HDIM + (w * 32 + lane) * 4;
                float4 v;
                for (;;) {
                    v = ld_volatile_f4(qp);
                    bool ok = (__float_as_uint(v.x) != SENT) &
                              (__float_as_uint(v.y) != SENT) &
                              (__float_as_uint(v.z) != SENT) &
                              (__float_as_uint(v.w) != SENT);
                    if (__all_sync(0xffffffffu, ok)) break;
                }
                s_h[w * 32 + lane] = v;
            }
            __syncthreads();                   // s_h ready (uniform branch)
            h0 = s_h[lane +  0];
            h1 = s_h[lane + 32];
            h2 = s_h[lane + 64];
            h3 = s_h[lane + 96];
        } else {
            h0 = h1 = h2 = h3 = make_float4(0.f, 0.f, 0.f, 0.f);
        }

        // --- 5 dot products (this unit's i,o,f,u,r rows) ---
        float acc[5];
#pragma unroll
        for (int g = 0; g < 5; g++) {
            float a0 = fmaf(wv[g][0].x, h0.x, fmaf(wv[g][0].y, h0.y,
                       fmaf(wv[g][0].z, h0.z, wv[g][0].w * h0.w)));
            float a1 = fmaf(wv[g][1].x, h1.x, fmaf(wv[g][1].y, h1.y,
                       fmaf(wv[g][1].z, h1.z, wv[g][1].w * h1.w)));
            float a2 = fmaf(wv[g][2].x, h2.x, fmaf(wv[g][2].y, h2.y,
                       fmaf(wv[g][2].z, h2.z, wv[g][2].w * h2.w)));
            float a3 = fmaf(wv[g][3].x, h3.x, fmaf(wv[g][3].y, h3.y,
                       fmaf(wv[g][3].z, h3.z, wv[g][3].w * h3.w)));
            acc[g] = (a0 + a1) + (a2 + a3);
        }

        // --- fused 5-way butterfly reduce ---
#pragma unroll
        for (int off = 16; off; off >>= 1) {
#pragma unroll
            for (int g = 0; g < 5; g++)
                acc[g] += __shfl_xor_sync(0xffffffffu, acc[g], off);
        }

        // --- gate math + direct publish (lane 0 of each warp) ---
        if (lane == 0) {
            float cpar = 0.0f;
            if (p >= 0) {
                if (p == t - 1) {
                    cpar = c_last;                       // chain fast path
                } else {
                    const float* cp = &g_C[(size_t)p * HDIM + unit];
                    do { cpar = ld_volatile_f(cp); }     // general tree
                    while (__float_as_uint(cpar) == SENT);
                }
            }
            float iv = sigm(acc[0] + xg[0]);
            float ov = sigm(acc[1] + xg[1]);
            float fv = sigm(acc[2] + xg[2]);
            float uv = tanhfast(acc[3] + xg[3]);
            float rv = sigm(acc[4] + xg[4]);
            float c  = desent(fmaf(fv, cpar, iv * uv));
            float hh = ov * tanhfast(c);
            float hf = desent(rv * hh + (1.0f - rv) * px);
            c_last = c;
            Hout[(size_t)t * HDIM + unit] = hf;          // publish (flag = value)
            g_C[(size_t)t * HDIM + unit] = c;            // off critical path
            // prefetch next node's static terms (hidden under next poll)
            if (t + 1 < NNODES) {
#pragma unroll
                for (int g = 0; g < 5; g++)
                    xg[g] = g_xgb[(size_t)(t + 1) * GDIM + g * HDIM + unit];
                px = g_pxb[(size_t)(t + 1) * HDIM + unit];
            }
        }

        // s_h reuse hazard exists only when the next parent is NOT node t
        // (then the next poll can succeed instantly and overwrite s_h while
        // slow warps still read it). Block-uniform condition; chain skips it.
        if (t + 1 < NNODES && p_next != t) __syncthreads();

        p = p_next;
        if (t + 1 == NNODES) break;
    }
}

extern "C" void kernel_launch(void* const* d_in, const int* in_sizes, int n_in,
                              void* d_out, int out_size) {
    const float* features = (const float*)d_in[0];
    const int*   parents  = (const int*)d_in[1];
    const float* Wpx      = (const float*)d_in[2];
    const float* bpx      = (const float*)d_in[3];
    const float* Wx       = (const float*)d_in[4];
    const float* bx       = (const float*)d_in[5];
    const float* Wh       = (const float*)d_in[6];
    const float* bh       = (const float*)d_in[7];
    float* Hout = (float*)d_out;

    float* d_pxb = nullptr;
    float* d_xgb = nullptr;
    float* d_C   = nullptr;
    cudaGetSymbolAddress((void**)&d_pxb, g_pxb);
    cudaGetSymbolAddress((void**)&d_xgb, g_xgb);
    cudaGetSymbolAddress((void**)&d_C,   g_C);

    // 1) sentinel-poison Hout and g_C (replay-safe readiness protocol)
    poison_kernel<<<(2 * NNODES * HDIM / 4) / 256, 256>>>((float4*)Hout,
                                                          (float4*)d_C);

    // 2) batched x-side projections
    dim3 gpx(HDIM / 128, NNODES / 128);
    sgemm_bt_bias<<<gpx, 256>>>(features, Wpx, bpx, nullptr, d_pxb,
                                NNODES, HDIM, FEATD);
    dim3 gxg(GDIM / 128, NNODES / 128);
    sgemm_bt_bias<<<gxg, 256>>>(features, Wx, bx, bh, d_xgb,
                                NNODES, GDIM, FEATD);

    // 3) serial recurrence (barrier-free dataflow, 64 co-resident CTAs)
    treelstm_seq_kernel<<<NCTA, NTHR>>>(Wh, parents, Hout);
}